// round 16
// baseline (speedup 1.0000x reference)
#include <cuda_runtime.h>
#include <cuda_fp16.h>
#include <cstdint>

#define NMAX_NODES 100000
#define IN_F 256
#define OUT_F 128
#define ELL_CAP 96

// ---------------- scratch (device globals; zero-initialized at load) -------
// INVARIANT: g_cursor is all-zero at kernel_launch entry (gather re-zeroes it).
__device__ int      g_cursor[NMAX_NODES];
__device__ int      g_ell[(size_t)NMAX_NODES * ELL_CAP];
// g_msgh[row*256 + 2f] = half2(mean_msg[f], var_msg[f])  (src norm baked in)
__device__ __half   g_msgh[(size_t)NMAX_NODES * 256];
// fp16 B fragment image: [ck16][wq8][j4][lane32][e2] half2s (128KB)
__device__ uint32_t g_Bfragh[32768];

// ---------------- fill (4 edges/thread, int4) + fused B-frag prep ----------
__global__ void fill_prep_kernel(const int* __restrict__ src,
                                 const int* __restrict__ dst, int E,
                                 const float* __restrict__ Wm,
                                 const float* __restrict__ Wv) {
    int tid = blockIdx.x * blockDim.x + threadIdx.x;

    // B fragment packing (first 32768 threads)
    if (tid < 32768) {
        int e    = tid & 1;
        int lane = (tid >> 1) & 31;
        int j    = (tid >> 6) & 3;
        int wq   = (tid >> 8) & 7;
        int ck   = tid >> 11;          // 0..15
        int tc = lane & 3, g = lane >> 2;
        int k = ck * 16 + tc * 2 + e * 8;
        int ncol = wq * 32 + j * 8 + g;
        int f = ncol >> 1;
        const float* W = (ncol & 1) ? Wv : Wm;
        float lo = W[k * OUT_F + f];
        float hi = W[(k + 1) * OUT_F + f];
        __half2 h = __floats2half2_rn(lo, hi);
        g_Bfragh[tid] = *(uint32_t*)&h;
    }

    // ELL fill: cursor ends as in-degree (cursor was zero at entry: invariant)
    int base = tid * 4;
    if (base >= E) return;
    if (base + 4 <= E) {
        int4 s = *(const int4*)(src + base);
        int4 t = *(const int4*)(dst + base);
        int p;
        p = atomicAdd(&g_cursor[t.x], 1); if (p < ELL_CAP) g_ell[(size_t)t.x * ELL_CAP + p] = s.x;
        p = atomicAdd(&g_cursor[t.y], 1); if (p < ELL_CAP) g_ell[(size_t)t.y * ELL_CAP + p] = s.y;
        p = atomicAdd(&g_cursor[t.z], 1); if (p < ELL_CAP) g_ell[(size_t)t.z * ELL_CAP + p] = s.z;
        p = atomicAdd(&g_cursor[t.w], 1); if (p < ELL_CAP) g_ell[(size_t)t.w * ELL_CAP + p] = s.w;
    } else {
        for (int i = base; i < E; i++) {
            int d = dst[i];
            int p = atomicAdd(&g_cursor[d], 1);
            if (p < ELL_CAP) g_ell[(size_t)d * ELL_CAP + p] = src[i];
        }
    }
}

// ---------------- fp16 mma.sync GEMM + message epilogue (R14/R11 exact) ----
// CTA: 64 rows x 256 cols (c=2f+h), 256 threads = 8 warps, warp tile 64x32,
// m16n8k16, K chunked by 32. 2 CTAs/SM. ONE barrier per chunk.
__global__ void __launch_bounds__(256, 2) gemm_msg_kernel(
    const float* __restrict__ feat, int N)
{
    __shared__ __align__(16) __half As[2][64 * 72];  // 144B stride, 9216B/buf

    const int tid  = threadIdx.x;
    const int warp = tid >> 5;
    const int lane = tid & 31;
    const int g    = lane >> 2;
    const int tc   = lane & 3;
    const int row0 = blockIdx.x * 64;

    float d[4][4][4];   // [mt][j][frag]
    #pragma unroll
    for (int mt = 0; mt < 4; mt++)
        #pragma unroll
        for (int j = 0; j < 4; j++)
            #pragma unroll
            for (int u = 0; u < 4; u++) d[mt][j][u] = 0.f;

    const int ar = tid >> 2;       // 0..63 row
    const int aq = tid & 3;        // 0..3 : 8-float piece
    float4 pre0, pre1;

    auto ldA = [&](int c) {
        int gr = row0 + ar; if (gr >= N) gr = N - 1;
        const float4* p = (const float4*)(feat + (size_t)gr * IN_F + c * 32 + aq * 8);
        pre0 = p[0]; pre1 = p[1];
    };
    auto stA = [&](int buf) {
        __half2 h0 = __floats2half2_rn(pre0.x, pre0.y);
        __half2 h1 = __floats2half2_rn(pre0.z, pre0.w);
        __half2 h2 = __floats2half2_rn(pre1.x, pre1.y);
        __half2 h3 = __floats2half2_rn(pre1.z, pre1.w);
        uint4 pk;
        pk.x = *(unsigned*)&h0; pk.y = *(unsigned*)&h1;
        pk.z = *(unsigned*)&h2; pk.w = *(unsigned*)&h3;
        *(uint4*)&As[buf][ar * 72 + aq * 8] = pk;
    };

    ldA(0);

    for (int c = 0; c < 8; c++) {
        const int buf = c & 1;
        stA(buf);
        __syncthreads();             // single barrier per chunk (R11 proof)
        if (c + 1 < 8) ldA(c + 1);   // A LDG in flight across compute

        const __half* Ab = &As[buf][0];
        #pragma unroll
        for (int kl2 = 0; kl2 < 2; kl2++) {
            const int ck = c * 2 + kl2;
            const uint2* bb = (const uint2*)(g_Bfragh + ((ck * 8 + warp) * 4) * 64) + lane;
            uint2 breg[4];
            #pragma unroll
            for (int j = 0; j < 4; j++) breg[j] = __ldg(bb + j * 32);

            uint32_t a[4][4];
            #pragma unroll
            for (int mt = 0; mt < 4; mt++) {
                const __half* ap0 = Ab + (mt * 16 + g) * 72 + kl2 * 16 + tc * 2;
                const __half* ap1 = ap0 + 8 * 72;
                a[mt][0] = *(const uint32_t*)(ap0);
                a[mt][1] = *(const uint32_t*)(ap1);
                a[mt][2] = *(const uint32_t*)(ap0 + 8);
                a[mt][3] = *(const uint32_t*)(ap1 + 8);
            }
            #pragma unroll
            for (int j = 0; j < 4; j++) {
                #pragma unroll
                for (int mt = 0; mt < 4; mt++) {
                    asm volatile(
                        "mma.sync.aligned.m16n8k16.row.col.f32.f16.f16.f32 "
                        "{%0,%1,%2,%3}, {%4,%5,%6,%7}, {%8,%9}, {%0,%1,%2,%3};"
                        : "+f"(d[mt][j][0]), "+f"(d[mt][j][1]),
                          "+f"(d[mt][j][2]), "+f"(d[mt][j][3])
                        : "r"(a[mt][0]), "r"(a[mt][1]), "r"(a[mt][2]), "r"(a[mt][3]),
                          "r"(breg[j].x), "r"(breg[j].y));
                }
            }
        }
    }

    // ---- epilogue: (d0,d1)=(mean,var) row r0; (d2,d3) row r0+8 ----
    #pragma unroll
    for (int mt = 0; mt < 4; mt++) {
        int r0 = row0 + mt * 16 + g;
        int r1 = r0 + 8;
        bool va = r0 < N, vb = r1 < N;
        float n1a = 0.f, n2a = 0.f, n1b = 0.f, n2b = 0.f;
        if (va) {
            int dg = g_cursor[r0];
            float df = (float)(dg > 0 ? dg : 1);
            n1a = rsqrtf(df); n2a = n1a * n1a;
        }
        if (vb) {
            int dg = g_cursor[r1];
            float df = (float)(dg > 0 ? dg : 1);
            n1b = rsqrtf(df); n2b = n1b * n1b;
        }
        #pragma unroll
        for (int j = 0; j < 4; j++) {
            int f = warp * 16 + j * 4 + tc;
            if (va) {
                float m = fmaxf(d[mt][j][0], 0.f);
                float v = fmaxf(d[mt][j][1], 0.f);
                float att = __expf(-v);
                __half2 h = __floats2half2_rn(m * att * n1a, v * att * att * n2a);
                *(__half2*)(g_msgh + (size_t)r0 * 256 + 2 * f) = h;
            }
            if (vb) {
                float m = fmaxf(d[mt][j][2], 0.f);
                float v = fmaxf(d[mt][j][3], 0.f);
                float att = __expf(-v);
                __half2 h = __floats2half2_rn(m * att * n1b, v * att * att * n2b);
                *(__half2*)(g_msgh + (size_t)r1 * 256 + 2 * f) = h;
            }
        }
    }
}

// ---------------- gather: one warp per dst node (R7 form) + cursor reset ---
__global__ void __launch_bounds__(256) gather_kernel(
    float* __restrict__ out_mean,
    float* __restrict__ out_var,
    int N)
{
    int warp = (blockIdx.x * blockDim.x + threadIdx.x) >> 5;
    int lane = threadIdx.x & 31;
    if (warp >= N) return;
    const int node = warp;

    int deg = g_cursor[node];
    if (lane == 0) g_cursor[node] = 0;     // restore invariant for next call
    int cnt_total = deg < ELL_CAP ? deg : ELL_CAP;

    float am0 = 0.f, am1 = 0.f, am2 = 0.f, am3 = 0.f;
    float av0 = 0.f, av1 = 0.f, av2 = 0.f, av3 = 0.f;

    const int* ell_row = g_ell + (size_t)node * ELL_CAP;

    for (int base = 0; base < cnt_total; base += 32) {
        int cnt = cnt_total - base; if (cnt > 32) cnt = 32;
        int s_l = (lane < cnt) ? ell_row[base + lane] : 0;
        #pragma unroll 4
        for (int e = 0; e < cnt; e++) {
            int s = __shfl_sync(0xffffffffu, s_l, e);
            uint4 q = *(const uint4*)(g_msgh + (size_t)s * 256 + lane * 8);
            float2 f0 = __half22float2(*(__half2*)&q.x);
            float2 f1 = __half22float2(*(__half2*)&q.y);
            float2 f2 = __half22float2(*(__half2*)&q.z);
            float2 f3 = __half22float2(*(__half2*)&q.w);
            am0 += f0.x; av0 += f0.y;
            am1 += f1.x; av1 += f1.y;
            am2 += f2.x; av2 += f2.y;
            am3 += f3.x; av3 += f3.y;
        }
    }

    float degf = (float)(deg > 0 ? deg : 1);
    float n1 = rsqrtf(degf);
    float n2 = n1 * n1;

    float4 om = make_float4(am0 * n1, am1 * n1, am2 * n1, am3 * n1);
    float4 ov = make_float4(av0 * n2, av1 * n2, av2 * n2, av3 * n2);
    *(float4*)(out_mean + (size_t)node * 128 + lane * 4) = om;
    *(float4*)(out_var  + (size_t)node * 128 + lane * 4) = ov;
}

// ---------------- launch: 3 kernels total ----------------
extern "C" void kernel_launch(void* const* d_in, const int* in_sizes, int n_in,
                              void* d_out, int out_size) {
    const float* feat = (const float*)d_in[0];
    const float* Wm   = (const float*)d_in[1];
    const float* Wv   = (const float*)d_in[2];
    const int*   src  = (const int*)d_in[3];
    const int*   dst  = (const int*)d_in[4];

    int N = in_sizes[0] / IN_F;           // 100000
    int E = in_sizes[3];                  // 1600000

    float* out      = (float*)d_out;
    float* out_mean = out;
    float* out_var  = out + (size_t)N * OUT_F;

    int fthreads = (E + 3) / 4;           // 400000 >= 32768 (prep coverage)
    fill_prep_kernel<<<(fthreads + 255) / 256, 256>>>(src, dst, E, Wm, Wv);

    gemm_msg_kernel<<<(N + 63) / 64, 256>>>(feat, N);

    int gblocks = (N * 32 + 255) / 256;
    gather_kernel<<<gblocks, 256>>>(out_mean, out_var, N);
}

// round 17
// speedup vs baseline: 1.6531x; 1.6531x over previous
#include <cuda_runtime.h>
#include <cuda_fp16.h>
#include <cstdint>

#define NMAX_NODES 100000
#define IN_F 256
#define OUT_F 128
#define ELL_CAP 96

// ---------------- scratch (device globals) ----------------
__device__ int      g_cursor[NMAX_NODES];                // in-degree after fill
__device__ int      g_ell[(size_t)NMAX_NODES * ELL_CAP];
// g_msgh[row*256 + 2f] = half2(mean_msg[f], var_msg[f])
__device__ __half   g_msgh[(size_t)NMAX_NODES * 256];
// fp16 B fragment image: [ck16][wq8][j4][lane32][e2] half2s (128KB)
__device__ uint32_t g_Bfragh[32768];

// ---------------- fused zero + B-fragment prep ----------------
__global__ void prep_kernel(const float* __restrict__ Wm,
                            const float* __restrict__ Wv, int n_nodes) {
    int tid = blockIdx.x * blockDim.x + threadIdx.x;
    if (tid < n_nodes) g_cursor[tid] = 0;
    if (tid < 32768) {
        int e    = tid & 1;
        int lane = (tid >> 1) & 31;
        int j    = (tid >> 6) & 3;
        int wq   = (tid >> 8) & 7;
        int ck   = tid >> 11;          // 0..15
        int tc = lane & 3, g = lane >> 2;
        int k = ck * 16 + tc * 2 + e * 8;
        int ncol = wq * 32 + j * 8 + g;
        int f = ncol >> 1;
        const float* W = (ncol & 1) ? Wv : Wm;
        float lo = W[k * OUT_F + f];
        float hi = W[(k + 1) * OUT_F + f];
        __half2 h = __floats2half2_rn(lo, hi);
        g_Bfragh[tid] = *(uint32_t*)&h;
    }
}

// ---------------- ELL fill: 4 edges per thread (int4 loads) ----------------
__global__ void fill_kernel(const int* __restrict__ src,
                            const int* __restrict__ dst, int E) {
    int i4 = blockIdx.x * blockDim.x + threadIdx.x;
    int base = i4 * 4;
    if (base >= E) return;
    if (base + 4 <= E) {
        int4 s = *(const int4*)(src + base);
        int4 t = *(const int4*)(dst + base);
        int p;
        p = atomicAdd(&g_cursor[t.x], 1); if (p < ELL_CAP) g_ell[(size_t)t.x * ELL_CAP + p] = s.x;
        p = atomicAdd(&g_cursor[t.y], 1); if (p < ELL_CAP) g_ell[(size_t)t.y * ELL_CAP + p] = s.y;
        p = atomicAdd(&g_cursor[t.z], 1); if (p < ELL_CAP) g_ell[(size_t)t.z * ELL_CAP + p] = s.z;
        p = atomicAdd(&g_cursor[t.w], 1); if (p < ELL_CAP) g_ell[(size_t)t.w * ELL_CAP + p] = s.w;
    } else {
        for (int i = base; i < E; i++) {
            int d = dst[i];
            int p = atomicAdd(&g_cursor[d], 1);
            if (p < ELL_CAP) g_ell[(size_t)d * ELL_CAP + p] = src[i];
        }
    }
}

// ---------------- fp16 mma.sync GEMM + message epilogue --------------------
// CTA: 64 rows x 256 cols (c=2f+h), 256 threads = 8 warps, warp tile 64x32,
// m16n8k16, K chunked by 32. 2 CTAs/SM. ONE barrier per chunk.
__global__ void __launch_bounds__(256, 2) gemm_msg_kernel(
    const float* __restrict__ feat, int N)
{
    __shared__ __align__(16) __half As[2][64 * 72];  // 144B stride, 9216B/buf

    const int tid  = threadIdx.x;
    const int warp = tid >> 5;      // 0..7 : col group of 32 (16 features)
    const int lane = tid & 31;
    const int g    = lane >> 2;     // 0..7
    const int tc   = lane & 3;      // 0..3
    const int row0 = blockIdx.x * 64;

    float d[4][4][4];   // [mt][j][frag]
    #pragma unroll
    for (int mt = 0; mt < 4; mt++)
        #pragma unroll
        for (int j = 0; j < 4; j++)
            #pragma unroll
            for (int u = 0; u < 4; u++) d[mt][j][u] = 0.f;

    const int ar = tid >> 2;       // 0..63 row
    const int aq = tid & 3;        // 0..3 : 8-float piece
    float4 pre0, pre1;

    auto ldA = [&](int c) {
        int gr = row0 + ar; if (gr >= N) gr = N - 1;
        const float4* p = (const float4*)(feat + (size_t)gr * IN_F + c * 32 + aq * 8);
        pre0 = p[0]; pre1 = p[1];
    };
    auto stA = [&](int buf) {
        __half2 h0 = __floats2half2_rn(pre0.x, pre0.y);
        __half2 h1 = __floats2half2_rn(pre0.z, pre0.w);
        __half2 h2 = __floats2half2_rn(pre1.x, pre1.y);
        __half2 h3 = __floats2half2_rn(pre1.z, pre1.w);
        uint4 pk;
        pk.x = *(unsigned*)&h0; pk.y = *(unsigned*)&h1;
        pk.z = *(unsigned*)&h2; pk.w = *(unsigned*)&h3;
        *(uint4*)&As[buf][ar * 72 + aq * 8] = pk;
    };

    ldA(0);

    for (int c = 0; c < 8; c++) {
        const int buf = c & 1;
        stA(buf);
        __syncthreads();             // single barrier per chunk (R11 proof)
        if (c + 1 < 8) ldA(c + 1);   // A LDG in flight across compute

        const __half* Ab = &As[buf][0];
        #pragma unroll
        for (int kl2 = 0; kl2 < 2; kl2++) {
            const int ck = c * 2 + kl2;
            const uint2* bb = (const uint2*)(g_Bfragh + ((ck * 8 + warp) * 4) * 64) + lane;
            uint2 breg[4];
            #pragma unroll
            for (int j = 0; j < 4; j++) breg[j] = __ldg(bb + j * 32);

            uint32_t a[4][4];
            #pragma unroll
            for (int mt = 0; mt < 4; mt++) {
                const __half* ap0 = Ab + (mt * 16 + g) * 72 + kl2 * 16 + tc * 2;
                const __half* ap1 = ap0 + 8 * 72;
                a[mt][0] = *(const uint32_t*)(ap0);
                a[mt][1] = *(const uint32_t*)(ap1);
                a[mt][2] = *(const uint32_t*)(ap0 + 8);
                a[mt][3] = *(const uint32_t*)(ap1 + 8);
            }
            #pragma unroll
            for (int j = 0; j < 4; j++) {
                #pragma unroll
                for (int mt = 0; mt < 4; mt++) {
                    asm volatile(
                        "mma.sync.aligned.m16n8k16.row.col.f32.f16.f16.f32 "
                        "{%0,%1,%2,%3}, {%4,%5,%6,%7}, {%8,%9}, {%0,%1,%2,%3};"
                        : "+f"(d[mt][j][0]), "+f"(d[mt][j][1]),
                          "+f"(d[mt][j][2]), "+f"(d[mt][j][3])
                        : "r"(a[mt][0]), "r"(a[mt][1]), "r"(a[mt][2]), "r"(a[mt][3]),
                          "r"(breg[j].x), "r"(breg[j].y));
                }
            }
        }
    }

    // ---- epilogue: (d0,d1)=(mean,var) row r0; (d2,d3) row r0+8 ----
    #pragma unroll
    for (int mt = 0; mt < 4; mt++) {
        int r0 = row0 + mt * 16 + g;
        int r1 = r0 + 8;
        bool va = r0 < N, vb = r1 < N;
        float n1a = 0.f, n2a = 0.f, n1b = 0.f, n2b = 0.f;
        if (va) {
            int dg = g_cursor[r0];
            float df = (float)(dg > 0 ? dg : 1);
            n1a = rsqrtf(df); n2a = n1a * n1a;
        }
        if (vb) {
            int dg = g_cursor[r1];
            float df = (float)(dg > 0 ? dg : 1);
            n1b = rsqrtf(df); n2b = n1b * n1b;
        }
        #pragma unroll
        for (int j = 0; j < 4; j++) {
            int f = warp * 16 + j * 4 + tc;
            if (va) {
                float m = fmaxf(d[mt][j][0], 0.f);
                float v = fmaxf(d[mt][j][1], 0.f);
                float att = __expf(-v);
                __half2 h = __floats2half2_rn(m * att * n1a, v * att * att * n2a);
                *(__half2*)(g_msgh + (size_t)r0 * 256 + 2 * f) = h;
            }
            if (vb) {
                float m = fmaxf(d[mt][j][2], 0.f);
                float v = fmaxf(d[mt][j][3], 0.f);
                float att = __expf(-v);
                __half2 h = __floats2half2_rn(m * att * n1b, v * att * att * n2b);
                *(__half2*)(g_msgh + (size_t)r1 * 256 + 2 * f) = h;
            }
        }
    }
}

// ---------------- gather: one warp per dst node (R7 form, FROZEN) ----------
__global__ void __launch_bounds__(256) gather_kernel(
    float* __restrict__ out_mean,
    float* __restrict__ out_var,
    int N)
{
    int warp = (blockIdx.x * blockDim.x + threadIdx.x) >> 5;
    int lane = threadIdx.x & 31;
    if (warp >= N) return;
    const int node = warp;

    int deg = g_cursor[node];
    int cnt_total = deg < ELL_CAP ? deg : ELL_CAP;

    float am0 = 0.f, am1 = 0.f, am2 = 0.f, am3 = 0.f;
    float av0 = 0.f, av1 = 0.f, av2 = 0.f, av3 = 0.f;

    const int* ell_row = g_ell + (size_t)node * ELL_CAP;

    for (int base = 0; base < cnt_total; base += 32) {
        int cnt = cnt_total - base; if (cnt > 32) cnt = 32;
        int s_l = (lane < cnt) ? ell_row[base + lane] : 0;
        #pragma unroll 4
        for (int e = 0; e < cnt; e++) {
            int s = __shfl_sync(0xffffffffu, s_l, e);
            uint4 q = *(const uint4*)(g_msgh + (size_t)s * 256 + lane * 8);
            float2 f0 = __half22float2(*(__half2*)&q.x);
            float2 f1 = __half22float2(*(__half2*)&q.y);
            float2 f2 = __half22float2(*(__half2*)&q.z);
            float2 f3 = __half22float2(*(__half2*)&q.w);
            am0 += f0.x; av0 += f0.y;
            am1 += f1.x; av1 += f1.y;
            am2 += f2.x; av2 += f2.y;
            am3 += f3.x; av3 += f3.y;
        }
    }

    float degf = (float)(deg > 0 ? deg : 1);
    float n1 = rsqrtf(degf);
    float n2 = n1 * n1;

    float4 om = make_float4(am0 * n1, am1 * n1, am2 * n1, am3 * n1);
    float4 ov = make_float4(av0 * n2, av1 * n2, av2 * n2, av3 * n2);
    *(float4*)(out_mean + (size_t)node * 128 + lane * 4) = om;
    *(float4*)(out_var  + (size_t)node * 128 + lane * 4) = ov;
}

// ---------------- launch ----------------
extern "C" void kernel_launch(void* const* d_in, const int* in_sizes, int n_in,
                              void* d_out, int out_size) {
    const float* feat = (const float*)d_in[0];
    const float* Wm   = (const float*)d_in[1];
    const float* Wv   = (const float*)d_in[2];
    const int*   src  = (const int*)d_in[3];
    const int*   dst  = (const int*)d_in[4];

    int N = in_sizes[0] / IN_F;           // 100000
    int E = in_sizes[3];                  // 1600000

    float* out      = (float*)d_out;
    float* out_mean = out;
    float* out_var  = out + (size_t)N * OUT_F;

    prep_kernel<<<(N + 255) / 256, 256>>>(Wm, Wv, N);

    int fthreads = (E + 3) / 4;
    fill_kernel<<<(fthreads + 255) / 256, 256>>>(src, dst, E);

    gemm_msg_kernel<<<(N + 63) / 64, 256>>>(feat, N);

    int gblocks = (N * 32 + 255) / 256;
    gather_kernel<<<gblocks, 256>>>(out_mean, out_var, N);
}